// round 10
// baseline (speedup 1.0000x reference)
#include <cuda_runtime.h>
#include <math.h>
#include <stdint.h>

#define AG    10
#define SEQ   50
#define IND   6
#define HID   64
#define OUTD  2
#define TDEC  60
#define BATCH 32768

#define NG      256   // 4*HID gate columns
#define MT      128   // batch rows per CTA
#define THREADS 512
#define AST     132   // A staging row stride in floats (pad vs 128)
#define KC      16    // K-chunk rows for weight streaming
#define NBUF    3     // cp.async ring depth

// Logical K per section and padded (multiple of KC) row counts
#define KE0 71
#define KE1 129
#define KD0 67
#define KD1 129
#define PE0 80
#define PE1 144
#define PD0 80
#define PD1 144

#define OFF_E0 0
#define OFF_E1 (PE0*NG)
#define OFF_D0 ((PE0+PE1)*NG)
#define OFF_D1 ((PE0+PE1+PD0)*NG)
#define WTOT   ((PE0+PE1+PD0+PD1)*NG)

typedef unsigned long long u64t;

// Pre-permuted, bias-folded weight scratch (gate-interleaved columns).
__device__ __align__(16) float g_W[WTOT];

// ---------------------------------------------------------------------------
// Prep kernel: build g_W.
// Column n = 4*j + q maps to gate row r = q*64 + j  (q: 0=i,1=f,2=g,3=o).
// Row 0 of each section = combined bias (A supplies a row of ones).
// ---------------------------------------------------------------------------
__global__ void prep_kernel(
    const float* __restrict__ eWih0, const float* __restrict__ eWhh0,
    const float* __restrict__ ebih0, const float* __restrict__ ebhh0,
    const float* __restrict__ eWih1, const float* __restrict__ eWhh1,
    const float* __restrict__ ebih1, const float* __restrict__ ebhh1,
    const float* __restrict__ dWih0, const float* __restrict__ dWhh0,
    const float* __restrict__ dbih0, const float* __restrict__ dbhh0,
    const float* __restrict__ dWih1, const float* __restrict__ dWhh1,
    const float* __restrict__ dbih1, const float* __restrict__ dbhh1)
{
    int idx = blockIdx.x * blockDim.x + threadIdx.x;
    if (idx >= WTOT) return;
    int n    = idx & (NG - 1);
    int grow = idx >> 8;
    int r    = ((n & 3) << 6) | (n >> 2);
    float v = 0.f;
    if (grow < PE0) {
        int row = grow;
        if      (row == 0)  v = ebih0[r] + ebhh0[r];
        else if (row <= 6)  v = eWih0[r * IND + (row - 1)];
        else if (row <= 70) v = eWhh0[r * HID + (row - 7)];
    } else if (grow < PE0 + PE1) {
        int row = grow - PE0;
        if      (row == 0)   v = ebih1[r] + ebhh1[r];
        else if (row <= 64)  v = eWih1[r * HID + (row - 1)];
        else if (row <= 128) v = eWhh1[r * HID + (row - 65)];
    } else if (grow < PE0 + PE1 + PD0) {
        int row = grow - (PE0 + PE1);
        if      (row == 0)  v = dbih0[r] + dbhh0[r];
        else if (row <= 2)  v = dWih0[r * OUTD + (row - 1)];
        else if (row <= 66) v = dWhh0[r * HID + (row - 3)];
    } else {
        int row = grow - (PE0 + PE1 + PD0);
        if      (row == 0)   v = dbih1[r] + dbhh1[r];
        else if (row <= 64)  v = dWih1[r * HID + (row - 1)];
        else if (row <= 128) v = dWhh1[r * HID + (row - 65)];
    }
    g_W[idx] = v;
}

// ---------------------------------------------------------------------------
// Device helpers
// ---------------------------------------------------------------------------
__device__ __forceinline__ float sigmf(float x) {
    return __fdividef(1.f, 1.f + __expf(-x));
}
// Robust tanh: 1 - 2/(e^{2x}+1). Handles |x| large without NaN.
__device__ __forceinline__ float tanhf_(float x) {
    float e = __expf(2.f * x);
    return 1.f - __fdividef(2.f, e + 1.f);
}

// Packed f32x2 helpers (Blackwell double-rate fp32 path).
__device__ __forceinline__ u64t dup2(float a) {
    u64t r;
    asm("mov.b64 %0, {%1, %1};" : "=l"(r) : "f"(a));
    return r;
}
__device__ __forceinline__ void fma2(u64t& d, u64t a, u64t b) {
    asm("fma.rn.f32x2 %0, %1, %2, %3;" : "=l"(d) : "l"(a), "l"(b), "l"(d));
}
__device__ __forceinline__ float2 unpk(u64t v) {
    float2 r;
    asm("mov.b64 {%0, %1}, %2;" : "=f"(r.x), "=f"(r.y) : "l"(v));
    return r;
}

// cp.async 16B global->shared (LDGSTS), L1-bypass.
__device__ __forceinline__ void cpa16(uint32_t saddr, const void* gaddr) {
    asm volatile("cp.async.cg.shared.global [%0], [%1], 16;\n"
                 :: "r"(saddr), "l"(gaddr));
}
#define CPA_COMMIT() asm volatile("cp.async.commit_group;\n" ::: "memory")
#define CPA_WAIT(N)  asm volatile("cp.async.wait_group %0;\n" :: "n"(N) : "memory")

// One k-row of FFMA2 work.
__device__ __forceinline__ void k_iter(const float* __restrict__ Arow,
                                       const float* __restrict__ Brow,
                                       u64t (&acc)[8][4], int tm0, int tn0)
{
    float4 a0 = *(const float4*)(Arow + tm0);
    float4 a1 = *(const float4*)(Arow + tm0 + 4);
    ulonglong2 b0 = *(const ulonglong2*)(Brow + tn0);
    ulonglong2 b1 = *(const ulonglong2*)(Brow + tn0 + 4);
    u64t bp[4] = {b0.x, b0.y, b1.x, b1.y};
    float av[8] = {a0.x, a0.y, a0.z, a0.w, a1.x, a1.y, a1.z, a1.w};
    #pragma unroll
    for (int i = 0; i < 8; i++) {
        u64t ad = dup2(av[i]);
        #pragma unroll
        for (int p = 0; p < 4; p++)
            fma2(acc[i][p], ad, bp[p]);
    }
}

// GEMM: packed acc[8][4] += A[K x 128] * B[K x 256].
// B streamed from g_W via cp.async through a 3-deep 16-row SMEM ring.
// Exactly ONE __syncthreads per chunk plus one tail barrier (the ring depth
// makes the second per-chunk barrier redundant: prefetch of chunk c+2 only
// overwrites buffer (c-1)%3, whose readers finished before this barrier).
__device__ __forceinline__ void do_gemm(const float* __restrict__ Bg, int K,
                                        const float* __restrict__ A,
                                        const float* __restrict__ Bs,
                                        uint32_t bsu,
                                        u64t (&acc)[8][4],
                                        int tid, int tm0, int tn0)
{
    const int nch = (K + KC - 1) >> 4;
    const float4* __restrict__ Bgv = (const float4*)Bg;
    const uint32_t so0 = bsu + (uint32_t)tid * 16u;
    const uint32_t so1 = so0 + (uint32_t)(THREADS * 16);
    const float4* g0 = Bgv + tid;
    const float4* g1 = Bgv + THREADS + tid;

    // prologue: stage chunks 0 and 1
    cpa16(so0, g0);
    cpa16(so1, g1);
    CPA_COMMIT();
    if (nch > 1) {
        cpa16(so0 + (uint32_t)(KC * NG * 4), g0 + 1024);
        cpa16(so1 + (uint32_t)(KC * NG * 4), g1 + 1024);
        CPA_COMMIT();
    }

    for (int c = 0; c < nch; c++) {
        if (c + 1 < nch) CPA_WAIT(1); else CPA_WAIT(0);
        __syncthreads();                       // chunk c visible; buffer
                                               // (c+2)%3 free for refill
        if (c + 2 < nch) {                     // stage chunk c+2 into ring
            uint32_t bd = (uint32_t)(((c + 2) % NBUF) * (KC * NG * 4));
            cpa16(so0 + bd, g0 + (size_t)(c + 2) * 1024);
            cpa16(so1 + bd, g1 + (size_t)(c + 2) * 1024);
            CPA_COMMIT();
        }
        const float* Bsc = Bs + (c % NBUF) * (KC * NG);
        const int kc   = c * KC;
        const float* Abase = A + (size_t)kc * AST;
        if (kc + KC <= K) {                    // full 16-row chunk (hot path)
            #pragma unroll 8
            for (int kk = 0; kk < KC; kk++)
                k_iter(Abase + kk * AST, Bsc + kk * NG, acc, tm0, tn0);
        } else {                               // short tail chunk
            const int kend = K - kc;
            for (int kk = 0; kk < kend; kk++)
                k_iter(Abase + kk * AST, Bsc + kk * NG, acc, tm0, tn0);
        }
    }
    __syncthreads();   // all reads of A / last buffers done before caller
                       // overwrites A or the next gemm refills buffer 0
}

// LSTM gate update. Thread owns 8 rows x 2 hidden cols. Packed acc layout:
// acc[i][p] holds cols (2p,2p+1); quad jj -> packs (2jj)=(i,f), (2jj+1)=(g,o).
// Cell state lives in SMEM (float2 per (i) per thread), registers stay lean.
template <bool L0>
__device__ __forceinline__ void do_update(u64t (&acc)[8][4],
                                          float2* __restrict__ csL,
                                          float* __restrict__ A1w,
                                          float* __restrict__ A0w, int xoff,
                                          int lane, int tm0)
{
    #pragma unroll
    for (int i = 0; i < 8; i++) {
        float2 cv = csL[i * THREADS];
        #pragma unroll
        for (int jj = 0; jj < 2; jj++) {
            float2 g_if = unpk(acc[i][jj * 2 + 0]);
            float2 g_go = unpk(acc[i][jj * 2 + 1]);
            float cprev = (jj == 0) ? cv.x : cv.y;
            float c = sigmf(g_if.y) * cprev + sigmf(g_if.x) * tanhf_(g_go.x);
            if (jj == 0) cv.x = c; else cv.y = c;
            float h = sigmf(g_go.y) * tanhf_(c);
            int j = lane * 2 + jj;
            int m = tm0 + i;
            if (L0) {
                A1w[(1 + j) * AST + m]    = h;   // layer-1 input slot
                A0w[(xoff + j) * AST + m] = h;   // own recurrence slot
            } else {
                A1w[(65 + j) * AST + m]   = h;   // own recurrence slot
            }
        }
        csL[i * THREADS] = cv;
    }
}

#define ZERO_ACC(acc) do {                          \
    _Pragma("unroll")                               \
    for (int _i = 0; _i < 8; _i++)                  \
        _Pragma("unroll")                           \
        for (int _p = 0; _p < 4; _p++)              \
            (acc)[_i][_p] = 0ull;                   \
} while (0)

// SMEM float counts
#define SM_A0  (KE0*AST)
#define SM_A1  (KE1*AST)
#define SM_BS  (NBUF*KC*NG)
#define SM_CS  (2*8*THREADS*2)
#define SM_TOT (SM_A0 + SM_A1 + SM_BS + SM_CS + 130)

// ---------------------------------------------------------------------------
// Main persistent-per-tile LSTM kernel. One CTA = 128 batch rows, 16 warps,
// full encoder + decoder recurrence with states resident in SMEM/registers.
// ---------------------------------------------------------------------------
__global__ void __launch_bounds__(THREADS, 1)
lstm_main(const float* __restrict__ hist, const float* __restrict__ linW,
          const float* __restrict__ linb, const float* __restrict__ start,
          float* __restrict__ out)
{
    extern __shared__ float sm[];
    float*  A0  = sm;                     // [KE0][AST]      layer0 input staging
    float*  A1  = A0 + SM_A0;             // [KE1][AST]      layer1 input staging
    float*  Bs  = A1 + SM_A1;             // [NBUF][KC][NG]  weight ring
    float*  csf = Bs + SM_BS;             // [2][8][THREADS] float2 cell state
    float*  lw  = csf + SM_CS;            // [2][64]         lin_W
    float*  lb  = lw + 128;               // [2]             lin_b

    const int tid  = threadIdx.x;
    const int lane = tid & 31;
    const int tm0  = (tid >> 5) * 8;
    const int tn0  = lane * 8;
    const int b0   = blockIdx.x * MT;

    uint32_t bsu;
    asm("{ .reg .u64 t; cvta.to.shared.u64 t, %1; cvt.u32.u64 %0, t; }"
        : "=r"(bsu) : "l"(Bs));

    float2* cs0 = (float2*)csf + tid;               // layer-0 state
    float2* cs1 = (float2*)csf + 8 * THREADS + tid; // layer-1 state

    for (int i = tid; i < SM_A0; i += THREADS) A0[i] = 0.f;
    for (int i = tid; i < SM_A1; i += THREADS) A1[i] = 0.f;
    for (int i = tid; i < SM_CS; i += THREADS) csf[i] = 0.f;
    if (tid < MT) { A0[tid] = 1.f; A1[tid] = 1.f; }   // ones row (bias feed)
    if (tid < 128) lw[tid] = linW[tid];
    if (tid < 2)   lb[tid] = linb[tid];
    __syncthreads();

    // ---------------- encoder: 50 steps ----------------
    for (int t = 0; t < SEQ; t++) {
        if (tid < MT) {
            const float* xp = hist + (size_t)(b0 + tid) * (AG * SEQ * IND) + t * IND;
            #pragma unroll
            for (int i = 0; i < IND; i++) A0[(1 + i) * AST + tid] = xp[i];
        }
        u64t acc[8][4];
        ZERO_ACC(acc);
        do_gemm(g_W + OFF_E0, KE0, A0, Bs, bsu, acc, tid, tm0, tn0);
        do_update<true>(acc, cs0, A1, A0, 7, lane, tm0);
        ZERO_ACC(acc);
        do_gemm(g_W + OFF_E1, KE1, A1, Bs, bsu, acc, tid, tm0, tn0);
        do_update<false>(acc, cs1, A1, A0, 0, lane, tm0);
        // next gemm's chunk-0 barrier orders these writes
    }

    // -------- phase switch: shift h0 rows 7..70 -> 3..66, set start token ----
    {
        __syncthreads();
        float tmp[16];
        #pragma unroll
        for (int e = 0; e < 16; e++) {
            int idx = tid + e * THREADS;       // 0..8191
            int k = idx >> 7, m = idx & 127;
            tmp[e] = A0[(7 + k) * AST + m];
        }
        __syncthreads();
        #pragma unroll
        for (int e = 0; e < 16; e++) {
            int idx = tid + e * THREADS;
            int k = idx >> 7, m = idx & 127;
            A0[(3 + k) * AST + m] = tmp[e];
        }
        if (tid < 2 * MT) {
            int o = tid >> 7, m = tid & 127;
            A0[(1 + o) * AST + m] = start[o];
        }
        __syncthreads();
    }

    // ---------------- decoder: 60 steps ----------------
    for (int t = 0; t < TDEC; t++) {
        u64t acc[8][4];
        ZERO_ACC(acc);
        do_gemm(g_W + OFF_D0, KD0, A0, Bs, bsu, acc, tid, tm0, tn0);
        do_update<true>(acc, cs0, A1, A0, 3, lane, tm0);
        ZERO_ACC(acc);
        do_gemm(g_W + OFF_D1, KD1, A1, Bs, bsu, acc, tid, tm0, tn0);
        do_update<false>(acc, cs1, A1, A0, 0, lane, tm0);
        __syncthreads();   // h1 writes visible to the epilogue readers
        // out = h1 @ lin_W^T + lin_b ; feed back as next x; store result
        if (tid < 2 * MT) {
            int o = tid >> 7, m = tid & 127;
            float s = lb[o];
            const float* lwo = lw + o * 64;
            #pragma unroll 8
            for (int k = 0; k < HID; k++)
                s = fmaf(lwo[k], A1[(65 + k) * AST + m], s);
            out[(size_t)(b0 + m) * (TDEC * OUTD) + t * OUTD + o] = s;
            A0[(1 + o) * AST + m] = s;
        }
        // next gemm D0's chunk-0 barrier orders the A0 feedback writes
    }
}

// ---------------------------------------------------------------------------
// Launch
// ---------------------------------------------------------------------------
extern "C" void kernel_launch(void* const* d_in, const int* in_sizes, int n_in,
                              void* d_out, int out_size)
{
    (void)in_sizes; (void)n_in; (void)out_size;
    const float* hist = (const float*)d_in[0];

    prep_kernel<<<(WTOT + 255) / 256, 256>>>(
        (const float*)d_in[1],  (const float*)d_in[2],
        (const float*)d_in[3],  (const float*)d_in[4],
        (const float*)d_in[5],  (const float*)d_in[6],
        (const float*)d_in[7],  (const float*)d_in[8],
        (const float*)d_in[9],  (const float*)d_in[10],
        (const float*)d_in[11], (const float*)d_in[12],
        (const float*)d_in[13], (const float*)d_in[14],
        (const float*)d_in[15], (const float*)d_in[16]);

    size_t smem = (size_t)SM_TOT * sizeof(float);
    cudaFuncSetAttribute(lstm_main, cudaFuncAttributeMaxDynamicSharedMemorySize,
                         (int)smem);
    lstm_main<<<BATCH / MT, THREADS, smem>>>(
        hist, (const float*)d_in[17], (const float*)d_in[18],
        (const float*)d_in[19], (float*)d_out);
}

// round 11
// speedup vs baseline: 1.0651x; 1.0651x over previous
#include <cuda_runtime.h>
#include <math.h>
#include <stdint.h>

#define AG    10
#define SEQ   50
#define IND   6
#define HID   64
#define OUTD  2
#define TDEC  60
#define BATCH 32768

#define NG      256   // 4*HID gate columns
#define MT      64    // batch rows per CTA
#define THREADS 256
#define AST     68    // staging row stride in floats (pad vs 64)
#define KC      16    // K-chunk rows for weight streaming
#define NBUF    2     // cp.async ring depth

// Unified staging row map: [0..5]=x/out, [6]=bias(ones), [7..70]=h0, [71..134]=h1
#define ROW_BIAS 6
#define ROW_H0   7
#define ROW_H1   71
#define STG_ROWS 136

// Logical K per section and padded (multiple of KC) row counts
#define KE0 71    // rows 0..70   (x, bias, h0)
#define KE1 129   // rows 6..134  (bias, h0, h1)
#define KD0 67    // rows 4..70   (out, bias, h0)
#define KD1 129   // rows 6..134
#define PE0 80
#define PE1 144
#define PD0 80
#define PD1 144

#define OFF_E0 0
#define OFF_E1 (PE0*NG)
#define OFF_D0 ((PE0+PE1)*NG)
#define OFF_D1 ((PE0+PE1+PD0)*NG)
#define WTOT   ((PE0+PE1+PD0+PD1)*NG)

typedef unsigned long long u64t;

// Pre-permuted, bias-folded weight scratch (gate-interleaved columns).
__device__ __align__(16) float g_W[WTOT];

// ---------------------------------------------------------------------------
// Prep kernel: build g_W. Column n = 4*j + q maps to gate row r = q*64 + j.
// Row ordering matches the unified staging layout per section.
// ---------------------------------------------------------------------------
__global__ void prep_kernel(
    const float* __restrict__ eWih0, const float* __restrict__ eWhh0,
    const float* __restrict__ ebih0, const float* __restrict__ ebhh0,
    const float* __restrict__ eWih1, const float* __restrict__ eWhh1,
    const float* __restrict__ ebih1, const float* __restrict__ ebhh1,
    const float* __restrict__ dWih0, const float* __restrict__ dWhh0,
    const float* __restrict__ dbih0, const float* __restrict__ dbhh0,
    const float* __restrict__ dWih1, const float* __restrict__ dWhh1,
    const float* __restrict__ dbih1, const float* __restrict__ dbhh1)
{
    int idx = blockIdx.x * blockDim.x + threadIdx.x;
    if (idx >= WTOT) return;
    int n    = idx & (NG - 1);
    int grow = idx >> 8;
    int r    = ((n & 3) << 6) | (n >> 2);
    float v = 0.f;
    if (grow < PE0) {                       // E0: [x(6) | bias | h0(64)]
        int row = grow;
        if      (row < 6)   v = eWih0[r * IND + row];
        else if (row == 6)  v = ebih0[r] + ebhh0[r];
        else if (row <= 70) v = eWhh0[r * HID + (row - 7)];
    } else if (grow < PE0 + PE1) {          // E1: [bias | h0(64) | h1(64)]
        int row = grow - PE0;
        if      (row == 0)   v = ebih1[r] + ebhh1[r];
        else if (row <= 64)  v = eWih1[r * HID + (row - 1)];
        else if (row <= 128) v = eWhh1[r * HID + (row - 65)];
    } else if (grow < PE0 + PE1 + PD0) {    // D0: [out(2) | bias | h0(64)]
        int row = grow - (PE0 + PE1);
        if      (row < 2)   v = dWih0[r * OUTD + row];
        else if (row == 2)  v = dbih0[r] + dbhh0[r];
        else if (row <= 66) v = dWhh0[r * HID + (row - 3)];
    } else {                                // D1: [bias | h0(64) | h1(64)]
        int row = grow - (PE0 + PE1 + PD0);
        if      (row == 0)   v = dbih1[r] + dbhh1[r];
        else if (row <= 64)  v = dWih1[r * HID + (row - 1)];
        else if (row <= 128) v = dWhh1[r * HID + (row - 65)];
    }
    g_W[idx] = v;
}

// ---------------------------------------------------------------------------
// Device helpers
// ---------------------------------------------------------------------------
__device__ __forceinline__ float sigmf(float x) {
    return __fdividef(1.f, 1.f + __expf(-x));
}
__device__ __forceinline__ float tanhf_(float x) {
    float e = __expf(2.f * x);
    return 1.f - __fdividef(2.f, e + 1.f);
}

// Packed f32x2 helpers (Blackwell double-rate fp32 path).
__device__ __forceinline__ u64t dup2(float a) {
    u64t r;
    asm("mov.b64 %0, {%1, %1};" : "=l"(r) : "f"(a));
    return r;
}
__device__ __forceinline__ void fma2(u64t& d, u64t a, u64t b) {
    asm("fma.rn.f32x2 %0, %1, %2, %3;" : "=l"(d) : "l"(a), "l"(b), "l"(d));
}
__device__ __forceinline__ float2 unpk(u64t v) {
    float2 r;
    asm("mov.b64 {%0, %1}, %2;" : "=f"(r.x), "=f"(r.y) : "l"(v));
    return r;
}

// cp.async 16B global->shared (LDGSTS), L1-bypass.
__device__ __forceinline__ void cpa16(uint32_t saddr, const void* gaddr) {
    asm volatile("cp.async.cg.shared.global [%0], [%1], 16;\n"
                 :: "r"(saddr), "l"(gaddr));
}
#define CPA_COMMIT() asm volatile("cp.async.commit_group;\n" ::: "memory")
#define CPA_WAIT(N)  asm volatile("cp.async.wait_group %0;\n" :: "n"(N) : "memory")

// One k-row of FFMA2 work.
__device__ __forceinline__ void k_iter(const float* __restrict__ Arow,
                                       const float* __restrict__ Brow,
                                       u64t (&acc)[8][4], int tm0, int tn0)
{
    float4 a0 = *(const float4*)(Arow + tm0);
    float4 a1 = *(const float4*)(Arow + tm0 + 4);
    ulonglong2 b0 = *(const ulonglong2*)(Brow + tn0);
    ulonglong2 b1 = *(const ulonglong2*)(Brow + tn0 + 4);
    u64t bp[4] = {b0.x, b0.y, b1.x, b1.y};
    float av[8] = {a0.x, a0.y, a0.z, a0.w, a1.x, a1.y, a1.z, a1.w};
    #pragma unroll
    for (int i = 0; i < 8; i++) {
        u64t ad = dup2(av[i]);
        #pragma unroll
        for (int p = 0; p < 4; p++)
            fma2(acc[i][p], ad, bp[p]);
    }
}

// GEMM: packed acc[8][4] += A[K x 64] * B[K x 256].
// B streamed via cp.async through a double-buffered 16-row SMEM ring,
// one __syncthreads per chunk (+1 tail). Safe with NBUF=2: prefetch of
// chunk c+1 overwrites chunk c-1's buffer, whose readers all passed the
// barrier at the top of iteration c.
__device__ __forceinline__ void do_gemm(const float* __restrict__ Bg, int K,
                                        const float* __restrict__ A,
                                        const float* __restrict__ Bs,
                                        uint32_t bsu,
                                        u64t (&acc)[8][4],
                                        int tid, int tm0, int tn0)
{
    const int nch = (K + KC - 1) >> 4;
    const float4* __restrict__ Bgv = (const float4*)Bg;
    const uint32_t s0 = bsu + (uint32_t)tid * 16u;

    // prologue: stage chunk 0 (1024 float4 across 256 threads = 4 each)
    #pragma unroll
    for (int e = 0; e < 4; e++)
        cpa16(s0 + (uint32_t)(e * THREADS * 16), Bgv + e * THREADS + tid);
    CPA_COMMIT();

    for (int c = 0; c < nch; c++) {
        CPA_WAIT(0);
        __syncthreads();                       // chunk c visible to all
        if (c + 1 < nch) {                     // prefetch next chunk
            uint32_t bd = (uint32_t)(((c + 1) & 1) * (KC * NG * 4));
            const float4* q = Bgv + (size_t)(c + 1) * 1024;
            #pragma unroll
            for (int e = 0; e < 4; e++)
                cpa16(s0 + bd + (uint32_t)(e * THREADS * 16), q + e * THREADS + tid);
            CPA_COMMIT();
        }
        const float* Bsc = Bs + (c & 1) * (KC * NG);
        const int kc = c * KC;
        const float* Abase = A + (size_t)kc * AST;
        if (kc + KC <= K) {                    // full 16-row chunk (hot path)
            #pragma unroll 8
            for (int kk = 0; kk < KC; kk++)
                k_iter(Abase + kk * AST, Bsc + kk * NG, acc, tm0, tn0);
        } else {                               // short tail chunk
            const int kend = K - kc;
            for (int kk = 0; kk < kend; kk++)
                k_iter(Abase + kk * AST, Bsc + kk * NG, acc, tm0, tn0);
        }
    }
    __syncthreads();   // reads of A / last buffer done before caller mutates
}

// LSTM gate update: thread owns 8 rows x 2 hidden cols; single h store into
// the unified staging buffer at row base (7 for layer0, 71 for layer1).
__device__ __forceinline__ void do_update(u64t (&acc)[8][4],
                                          float2* __restrict__ csL,
                                          float* __restrict__ stg, int rbase,
                                          int lane, int tm0)
{
    #pragma unroll
    for (int i = 0; i < 8; i++) {
        float2 cv = csL[i * THREADS];
        #pragma unroll
        for (int jj = 0; jj < 2; jj++) {
            float2 g_if = unpk(acc[i][jj * 2 + 0]);
            float2 g_go = unpk(acc[i][jj * 2 + 1]);
            float cprev = (jj == 0) ? cv.x : cv.y;
            float c = sigmf(g_if.y) * cprev + sigmf(g_if.x) * tanhf_(g_go.x);
            if (jj == 0) cv.x = c; else cv.y = c;
            float h = sigmf(g_go.y) * tanhf_(c);
            stg[(rbase + lane * 2 + jj) * AST + (tm0 + i)] = h;
        }
        csL[i * THREADS] = cv;
    }
}

#define ZERO_ACC(acc) do {                          \
    _Pragma("unroll")                               \
    for (int _i = 0; _i < 8; _i++)                  \
        _Pragma("unroll")                           \
        for (int _p = 0; _p < 4; _p++)              \
            (acc)[_i][_p] = 0ull;                   \
} while (0)

// SMEM float counts
#define SM_STG (STG_ROWS*AST)
#define SM_BS  (NBUF*KC*NG)
#define SM_CS  (2*8*THREADS*2)
#define SM_TOT (SM_STG + SM_BS + SM_CS + 130)

// ---------------------------------------------------------------------------
// Main kernel. One CTA = 64 batch rows, 8 warps; TWO CTAs co-resident per SM
// in independent barrier domains (odd CTAs staggered anti-phase) so one CTA's
// MUFU epilogue overlaps the other's FFMA2 GEMM.
// ---------------------------------------------------------------------------
__global__ void __launch_bounds__(THREADS, 2)
lstm_main(const float* __restrict__ hist, const float* __restrict__ linW,
          const float* __restrict__ linb, const float* __restrict__ start,
          float* __restrict__ out)
{
    extern __shared__ float sm[];
    float*  stg = sm;                     // [STG_ROWS][AST] unified staging
    float*  Bs  = stg + SM_STG;           // [NBUF][KC][NG]  weight ring
    float*  csf = Bs + SM_BS;             // [2][8][THREADS] float2 cell state
    float*  lw  = csf + SM_CS;            // [2][64]         lin_W
    float*  lb  = lw + 128;               // [2]             lin_b

    const int tid  = threadIdx.x;
    const int lane = tid & 31;
    const int tm0  = (tid >> 5) * 8;
    const int tn0  = lane * 8;
    const int b0   = blockIdx.x * MT;

    uint32_t bsu;
    asm("{ .reg .u64 t; cvta.to.shared.u64 t, %1; cvt.u32.u64 %0, t; }"
        : "=r"(bsu) : "l"(Bs));

    float2* cs0 = (float2*)csf + tid;               // layer-0 state
    float2* cs1 = (float2*)csf + 8 * THREADS + tid; // layer-1 state

    for (int i = tid; i < SM_STG; i += THREADS) stg[i] = 0.f;
    for (int i = tid; i < SM_CS;  i += THREADS) csf[i] = 0.f;
    if (tid < MT)  stg[ROW_BIAS * AST + tid] = 1.f;   // ones row (bias feed)
    if (tid < 128) lw[tid] = linW[tid];
    if (tid < 2)   lb[tid] = linb[tid];
    __syncthreads();

    // ---- anti-phase stagger: odd CTAs burn ~half a step on a dummy GEMM ----
    if (blockIdx.x & 1) {
        u64t dacc[8][4];
        ZERO_ACC(dacc);
        do_gemm(g_W + OFF_E1, KE1, stg + ROW_BIAS * AST, Bs, bsu, dacc,
                tid, tm0, tn0);
        float s = 0.f;
        #pragma unroll
        for (int i = 0; i < 8; i++)
            #pragma unroll
            for (int p = 0; p < 4; p++) {
                float2 v = unpk(dacc[i][p]);
                s += v.x + v.y;
            }
        if (__float_as_uint(s) == 0xdeadbeefu)      // never true; keeps FMAs
            stg[(STG_ROWS - 1) * AST] = s;
        __syncthreads();
    }

    // ---------------- encoder: 50 steps ----------------
    for (int t = 0; t < SEQ; t++) {
        if (tid < MT) {
            const float* xp = hist + (size_t)(b0 + tid) * (AG * SEQ * IND) + t * IND;
            #pragma unroll
            for (int i = 0; i < IND; i++) stg[i * AST + tid] = xp[i];
        }
        u64t acc[8][4];
        ZERO_ACC(acc);
        do_gemm(g_W + OFF_E0, KE0, stg, Bs, bsu, acc, tid, tm0, tn0);
        do_update(acc, cs0, stg, ROW_H0, lane, tm0);
        ZERO_ACC(acc);
        do_gemm(g_W + OFF_E1, KE1, stg + ROW_BIAS * AST, Bs, bsu, acc, tid, tm0, tn0);
        do_update(acc, cs1, stg, ROW_H1, lane, tm0);
        // next gemm's chunk-0 barrier orders these writes
    }

    // -------- phase switch: just drop the start token into rows 4..5 --------
    __syncthreads();
    if (tid < 2 * MT) {
        int o = tid >> 6, m = tid & 63;
        stg[(4 + o) * AST + m] = start[o];
    }
    __syncthreads();

    // ---------------- decoder: 60 steps ----------------
    for (int t = 0; t < TDEC; t++) {
        u64t acc[8][4];
        ZERO_ACC(acc);
        do_gemm(g_W + OFF_D0, KD0, stg + 4 * AST, Bs, bsu, acc, tid, tm0, tn0);
        do_update(acc, cs0, stg, ROW_H0, lane, tm0);
        ZERO_ACC(acc);
        do_gemm(g_W + OFF_D1, KD1, stg + ROW_BIAS * AST, Bs, bsu, acc, tid, tm0, tn0);
        do_update(acc, cs1, stg, ROW_H1, lane, tm0);
        __syncthreads();   // h1 writes visible to the epilogue readers
        // out = h1 @ lin_W^T + lin_b ; feed back as next x; store result
        if (tid < 2 * MT) {
            int o = tid >> 6, m = tid & 63;
            float s = lb[o];
            const float* lwo = lw + o * 64;
            #pragma unroll 8
            for (int k = 0; k < HID; k++)
                s = fmaf(lwo[k], stg[(ROW_H1 + k) * AST + m], s);
            out[(size_t)(b0 + m) * (TDEC * OUTD) + t * OUTD + o] = s;
            stg[(4 + o) * AST + m] = s;
        }
        // next gemm D0's chunk-0 barrier orders the feedback writes
    }
}

// ---------------------------------------------------------------------------
// Launch
// ---------------------------------------------------------------------------
extern "C" void kernel_launch(void* const* d_in, const int* in_sizes, int n_in,
                              void* d_out, int out_size)
{
    (void)in_sizes; (void)n_in; (void)out_size;
    const float* hist = (const float*)d_in[0];

    prep_kernel<<<(WTOT + 255) / 256, 256>>>(
        (const float*)d_in[1],  (const float*)d_in[2],
        (const float*)d_in[3],  (const float*)d_in[4],
        (const float*)d_in[5],  (const float*)d_in[6],
        (const float*)d_in[7],  (const float*)d_in[8],
        (const float*)d_in[9],  (const float*)d_in[10],
        (const float*)d_in[11], (const float*)d_in[12],
        (const float*)d_in[13], (const float*)d_in[14],
        (const float*)d_in[15], (const float*)d_in[16]);

    size_t smem = (size_t)SM_TOT * sizeof(float);
    cudaFuncSetAttribute(lstm_main, cudaFuncAttributeMaxDynamicSharedMemorySize,
                         (int)smem);
    lstm_main<<<BATCH / MT, THREADS, smem>>>(
        hist, (const float*)d_in[17], (const float*)d_in[18],
        (const float*)d_in[19], (float*)d_out);
}